// round 13
// baseline (speedup 1.0000x reference)
#include <cuda_runtime.h>
#include <cstdint>

// ---------------- problem constants ----------------
#define CIN   128
#define COUT  256
#define DTOT  1152
#define RCH   18
#define NCTA  296            // 2 per SM x 148 SMs, single wave
#define NTILES 4096          // (16384/16) pixel groups x (256/64) channel groups
#define STRIPE 512           // NTILES / 8 warp slots

#define PADROW 36
#define PADIMG (34 * PADROW)

// ---------------- device scratch ----------------
__device__ unsigned g_mm[2] = {0u, 0u};
__device__ unsigned g_tick[8];
__device__ __align__(16) signed char g_wq[RCH * 256 * 64];       // [r][m][64] permuted words
__device__ __align__(16) signed char g_xq[(size_t)RCH * 3 * 16384 * 64]; // [r][pl][pix][64] permuted
__device__ __align__(16) float g_xpad[16 * 128 * PADIMG];
__device__ int   g_ctab[DTOT];

// ---------------- helpers ----------------
__device__ __forceinline__ unsigned encf(float f) {
    int b = __float_as_int(f);
    return (b < 0) ? ~(unsigned)b : ((unsigned)b | 0x80000000u);
}
__device__ __forceinline__ float decf(unsigned u) {
    int b = (u & 0x80000000u) ? (int)(u & 0x7fffffffu) : ~(int)u;
    return __int_as_float(b);
}
__device__ __forceinline__ void imma(int* d, unsigned a0, unsigned a1,
                                     unsigned a2, unsigned a3,
                                     unsigned b0, unsigned b1) {
    asm volatile(
        "mma.sync.aligned.m16n8k32.row.col.s32.s8.s8.s32 "
        "{%0,%1,%2,%3}, {%4,%5,%6,%7}, {%8,%9}, {%0,%1,%2,%3};"
        : "+r"(d[0]), "+r"(d[1]), "+r"(d[2]), "+r"(d[3])
        : "r"(a0), "r"(a1), "r"(a2), "r"(a3), "r"(b0), "r"(b1));
}
__device__ __forceinline__ unsigned prmt(unsigned a, unsigned b, unsigned c) {
    unsigned r;
    asm("prmt.b32 %0, %1, %2, %3;" : "=r"(r) : "r"(a), "r"(b), "r"(c));
    return r;
}
__device__ __forceinline__ unsigned pack_b0(int v0, int v1, int v2, int v3) {
    return prmt(prmt((unsigned)v0, (unsigned)v1, 0x0040),
                prmt((unsigned)v2, (unsigned)v3, 0x0040), 0x5410);
}
// bytes = 1 where v_q >= 0, at byte position q
__device__ __forceinline__ unsigned sign_inc(int v0, int v1, int v2, int v3) {
    unsigned s01 = prmt((unsigned)v0, (unsigned)v1, 0x00FB);
    unsigned s23 = prmt((unsigned)v2, (unsigned)v3, 0x00FB);
    return ~prmt(s01, s23, 0x5410) & 0x01010101u;
}

// ---------------- pre-kernels ----------------
__global__ void k_minmax(const float* __restrict__ w, int n) {
    unsigned mx = 0u, mn = 0u;
    for (int i = blockIdx.x * blockDim.x + threadIdx.x; i < n;
         i += gridDim.x * blockDim.x) {
        float f = w[i];
        unsigned e0 = encf(f), e1 = encf(-f);
        mx = mx > e0 ? mx : e0;
        mn = mn > e1 ? mn : e1;
    }
    #pragma unroll
    for (int o = 16; o; o >>= 1) {
        unsigned a = __shfl_xor_sync(0xffffffffu, mx, o);
        unsigned b = __shfl_xor_sync(0xffffffffu, mn, o);
        mx = mx > a ? mx : a;
        mn = mn > b ? mn : b;
    }
    if ((threadIdx.x & 31) == 0) {
        atomicMax(&g_mm[0], mx);
        atomicMax(&g_mm[1], mn);
    }
}

// quantize to s8, layout [r][m][64] with word permutation p = 4*(W&3)+(W>>2)
__global__ void k_quant(const float* __restrict__ w) {
    int idx = blockIdx.x * blockDim.x + threadIdx.x;
    if (idx >= COUT * DTOT) return;
    float mx = decf(g_mm[0]);
    float mn = -decf(g_mm[1]);
    float scale = 15.0f / (mx - mn + 1e-9f);
    int m = idx / DTOT;
    int d = idx - m * DTOT;
    float q = fminf(fmaxf(rintf(w[idx] * scale), -7.0f), 7.0f);
    int r = d >> 6, kk = d & 63;
    int W = kk >> 2;
    int p = 4 * (W & 3) + (W >> 2);
    g_wq[r * 16384 + m * 64 + p * 4 + (kk & 3)] = (signed char)(int)q;
}

// zero-padded input copy (float4 stores) + offset table + ticket reset
__global__ void k_pad(const float* __restrict__ inp) {
    int idx = blockIdx.x * blockDim.x + threadIdx.x;
    if (idx < 8) g_tick[idx] = (unsigned)NCTA;
    if (idx < DTOT) {
        int c = idx / 9, e = idx - 9 * c;
        int dy = e / 3, dx = e - 3 * dy;
        g_ctab[idx] = c * PADIMG + dy * PADROW + dx;
    }
    const int N4 = 16 * 128 * (PADIMG / 4);
    if (idx >= N4) return;
    int bc  = idx / (PADIMG / 4);
    int rem = idx - bc * (PADIMG / 4);
    int yy  = rem / (PADROW / 4);
    int c4  = rem - yy * (PADROW / 4);
    const float* src = inp + bc * 1024 + (yy - 1) * 32;
    float4 v;
    #pragma unroll
    for (int j = 0; j < 4; j++) {
        int x = c4 * 4 + j;
        float f = 0.0f;
        if ((unsigned)(yy - 1) < 32u && (unsigned)(x - 1) < 32u)
            f = src[x - 1];
        ((float*)&v)[j] = f;
    }
    *(float4*)&g_xpad[(size_t)bc * PADIMG + yy * PADROW + c4 * 4] = v;
}

// im2col + exact 3-plane split, words stored permuted (p = 4*(W&3)+(W>>2))
__global__ __launch_bounds__(256)
void k_im2col() {
    __shared__ int s_ct[64];
    const int bid = blockIdx.x;                 // 0..1151
    const int r   = bid >> 6;
    const int pix = ((bid & 63) << 8) + threadIdx.x;
    const int b   = pix >> 10;
    const int p10 = pix & 1023;
    const int py  = p10 >> 5;
    const int px  = p10 & 31;
    const float* __restrict__ xb =
        g_xpad + (size_t)b * (128 * PADIMG) + py * PADROW + px;

    if (threadIdx.x < 64) s_ct[threadIdx.x] = g_ctab[r * 64 + threadIdx.x];
    __syncthreads();

    unsigned lo16[16], md16[16], hi16[16];
    #pragma unroll
    for (int W = 0; W < 16; W++) {
        int vi[4];
        #pragma unroll
        for (int e = 0; e < 4; e++) {
            float v = xb[s_ct[W * 4 + e]];
            vi[e] = __float2int_rn(v * 524288.0f);
        }
        int t0 = (vi[0] + 128) >> 8, t1 = (vi[1] + 128) >> 8;
        int t2 = (vi[2] + 128) >> 8, t3 = (vi[3] + 128) >> 8;
        int u0 = (t0 + 128) >> 8, u1 = (t1 + 128) >> 8;
        int u2 = (t2 + 128) >> 8, u3 = (t3 + 128) >> 8;
        const int p = 4 * (W & 3) + (W >> 2);
        lo16[p] = pack_b0(vi[0], vi[1], vi[2], vi[3]);
        md16[p] = pack_b0(t0, t1, t2, t3);
        hi16[p] = pack_b0(u0, u1, u2, u3);
    }
    size_t base = (((size_t)r * 3 + 0) << 20) + (size_t)pix * 64;
    #pragma unroll
    for (int i = 0; i < 4; i++)
        *(uint4*)&g_xq[base + i * 16] =
            make_uint4(hi16[i*4], hi16[i*4+1], hi16[i*4+2], hi16[i*4+3]);
    base = (((size_t)r * 3 + 1) << 20) + (size_t)pix * 64;
    #pragma unroll
    for (int i = 0; i < 4; i++)
        *(uint4*)&g_xq[base + i * 16] =
            make_uint4(md16[i*4], md16[i*4+1], md16[i*4+2], md16[i*4+3]);
    base = (((size_t)r * 3 + 2) << 20) + (size_t)pix * 64;
    #pragma unroll
    for (int i = 0; i < 4; i++)
        *(uint4*)&g_xq[base + i * 16] =
            make_uint4(lo16[i*4], lo16[i*4+1], lo16[i*4+2], lo16[i*4+3]);
}

// ---------------- main kernel: 16x64 tiles, per-wid work stealing ----------------
__global__ __launch_bounds__(256, 2)
void k_onn_main(float* __restrict__ out) {
    const int tid  = threadIdx.x;
    const int lane = tid & 31;
    const int wid  = tid >> 5;
    const int bid  = blockIdx.x;

    const signed char* __restrict__ xq = g_xq;
    const signed char* __restrict__ wq = g_wq;

    const unsigned laneq = (unsigned)(lane >> 2);   // row/col within fragment
    const unsigned lanec = (unsigned)(lane & 3) * 16u;

    int idx = bid;                        // static first tile
    while (idx < STRIPE) {
        const int tile = idx * 8 + wid;   // stripe: tiles == wid (mod 8)
        const int gp0  = (tile >> 2) * 16;
        const int ch0  = (tile & 3) * 64;

        const unsigned aoff_lo = (unsigned)(gp0 + (int)laneq) * 64u + lanec;
        const unsigned aoff_hi = aoff_lo + 8 * 64u;

        unsigned cnt[8];
        #pragma unroll
        for (int i = 0; i < 8; i++) cnt[i] = 0u;

        #pragma unroll 1
        for (int r = 0; r < RCH; r++) {
            // ---- A: 4 x LDG.128 ----
            uint4 alo[2], ahi[2];
            #pragma unroll
            for (int pl = 0; pl < 2; pl++) {
                const unsigned pb = (unsigned)(r * 3 + pl) << 20;
                alo[pl] = *(const uint4*)(xq + pb + aoff_lo);
                ahi[pl] = *(const uint4*)(xq + pb + aoff_hi);
            }
            // ---- B: 8 x LDG.128 ----
            uint4 bv[8];
            #pragma unroll
            for (int g = 0; g < 8; g++) {
                const unsigned col = (unsigned)(ch0 + g * 8) + laneq;
                bv[g] = *(const uint4*)(wq + (unsigned)r * 16384u + col * 64u + lanec);
            }

            // ---- compute: 8 accumulators (one per 8-channel group) ----
            unsigned cm = 0u;
            #pragma unroll
            for (int g = 0; g < 8; g++) {
                int acc[4] = {0, 0, 0, 0};
                #pragma unroll
                for (int pl = 0; pl < 2; pl++) {
                    if (pl) {
                        acc[0] <<= 8; acc[1] <<= 8; acc[2] <<= 8; acc[3] <<= 8;
                    }
                    imma(acc, alo[pl].x, ahi[pl].x, alo[pl].y, ahi[pl].y,
                         bv[g].x, bv[g].y);
                    imma(acc, alo[pl].z, ahi[pl].z, alo[pl].w, ahi[pl].w,
                         bv[g].z, bv[g].w);
                }
                cnt[g] += sign_inc(acc[0], acc[1], acc[2], acc[3]);
                #pragma unroll
                for (int q = 0; q < 4; q++)
                    if ((unsigned)(acc[q] + 224) <= 448u) cm |= 1u << (g * 4 + q);
                // stash acc for potential fixup via recompute-free path:
                // (rare) handle immediately to avoid keeping acc live
                while (cm) {
                    const int i = __ffs(cm) - 1;
                    cm &= cm - 1;
                    const int q = i & 3;          // i>>2 == g here
                    const int row = gp0 + (int)laneq + ((q & 2) ? 8 : 0);
                    const int col = ch0 + g * 8 + 2 * (lane & 3) + (q & 1);
                    const uint4* xl4 = (const uint4*)
                        (xq + ((unsigned)(r * 3 + 2) << 20) + (unsigned)row * 64u);
                    const uint4* wc4 = (const uint4*)
                        (wq + (unsigned)r * 16384u + (unsigned)col * 64u);
                    int slo = 0;
                    #pragma unroll
                    for (int kk = 0; kk < 4; kk++) {
                        uint4 xv = xl4[kk], wv = wc4[kk];
                        slo = __dp4a((int)xv.x, (int)wv.x, slo);
                        slo = __dp4a((int)xv.y, (int)wv.y, slo);
                        slo = __dp4a((int)xv.z, (int)wv.z, slo);
                        slo = __dp4a((int)xv.w, (int)wv.w, slo);
                    }
                    const int S = (acc[q] << 8) + slo;
                    const unsigned ob = (unsigned)(~acc[q]) >> 31;
                    const unsigned nb = (unsigned)(~S) >> 31;
                    cnt[g] += (nb - ob) << (8 * q);
                }
            }
        }

        // ---- store: 32 direct STG (sector-aligned: 8 consecutive pixels) ----
        const int b   = gp0 >> 10;
        const int p10 = gp0 & 1023;
        float* __restrict__ ob = out + (size_t)b * (COUT * 1024) + p10;
        #pragma unroll
        for (int g = 0; g < 8; g++) {
            const int ch = ch0 + g * 8 + 2 * (lane & 3);
            #pragma unroll
            for (int q = 0; q < 4; q++) {
                const int cc = ch + (q & 1);
                const int pp = (int)laneq + ((q & 2) ? 8 : 0);
                ob[(size_t)cc * 1024 + pp] =
                    (float)((cnt[g] >> (8 * q)) & 255u);
            }
        }

        // ---- steal next tile ----
        if (lane == 0) idx = (int)atomicAdd(&g_tick[wid], 1u);
        idx = __shfl_sync(0xffffffffu, idx, 0);
    }
}

// ---------------- launcher ----------------
extern "C" void kernel_launch(void* const* d_in, const int* in_sizes, int n_in,
                              void* d_out, int out_size) {
    const float* inp    = (const float*)d_in[0];  // [16,128,32,32]
    const float* weight = (const float*)d_in[1];  // [256,128,3,3]
    float* out          = (float*)d_out;          // [16,256,32,32]

    const int nw = COUT * DTOT;
    const int n4 = 16 * 128 * (PADIMG / 4);

    k_minmax<<<256, 256>>>(weight, nw);
    k_quant<<<(nw + 255) / 256, 256>>>(weight);
    k_pad<<<(n4 + 255) / 256, 256>>>(inp);
    k_im2col<<<RCH * 64, 256>>>();
    k_onn_main<<<NCTA, 256>>>(out);
}

// round 14
// speedup vs baseline: 1.6215x; 1.6215x over previous
#include <cuda_runtime.h>
#include <cstdint>

// ---------------- problem constants ----------------
#define CIN   128
#define COUT  256
#define DTOT  1152
#define RCH   18
#define NCTA  296            // 2 per SM x 148 SMs, single wave
#define NTILES 4096          // (16384/16) pixel groups x (256/64) channel groups

#define PADROW 36            // padded row stride, float4-aligned
#define PADIMG (34 * PADROW)

// ---------------- device scratch ----------------
__device__ unsigned g_mm[2] = {0u, 0u};
__device__ unsigned g_tick;
__device__ __align__(16) signed char g_wq[RCH * 4 * 256 * 16];   // [r][seg][m][16]
__device__ __align__(16) signed char g_xq[(size_t)RCH * 3 * 4 * 16384 * 16]; // [r][pl][seg][pix][16]
__device__ __align__(16) float g_xpad[16 * 128 * PADIMG];
__device__ int   g_ctab[DTOT];

// ---------------- helpers ----------------
__device__ __forceinline__ unsigned encf(float f) {
    int b = __float_as_int(f);
    return (b < 0) ? ~(unsigned)b : ((unsigned)b | 0x80000000u);
}
__device__ __forceinline__ float decf(unsigned u) {
    int b = (u & 0x80000000u) ? (int)(u & 0x7fffffffu) : ~(int)u;
    return __int_as_float(b);
}
__device__ __forceinline__ void imma(int* d, const unsigned* a, const unsigned* b) {
    asm volatile(
        "mma.sync.aligned.m16n8k32.row.col.s32.s8.s8.s32 "
        "{%0,%1,%2,%3}, {%4,%5,%6,%7}, {%8,%9}, {%0,%1,%2,%3};"
        : "+r"(d[0]), "+r"(d[1]), "+r"(d[2]), "+r"(d[3])
        : "r"(a[0]), "r"(a[1]), "r"(a[2]), "r"(a[3]),
          "r"(b[0]), "r"(b[1]));
}
__device__ __forceinline__ unsigned prmt(unsigned a, unsigned b, unsigned c) {
    unsigned r;
    asm("prmt.b32 %0, %1, %2, %3;" : "=r"(r) : "r"(a), "r"(b), "r"(c));
    return r;
}
__device__ __forceinline__ unsigned pack_b0(int v0, int v1, int v2, int v3) {
    return prmt(prmt((unsigned)v0, (unsigned)v1, 0x0040),
                prmt((unsigned)v2, (unsigned)v3, 0x0040), 0x5410);
}

// ---------------- pre-kernels (R12-proven versions) ----------------
__global__ void k_minmax(const float* __restrict__ w, int n) {
    unsigned mx = 0u, mn = 0u;
    for (int i = blockIdx.x * blockDim.x + threadIdx.x; i < n;
         i += gridDim.x * blockDim.x) {
        float f = w[i];
        unsigned e0 = encf(f), e1 = encf(-f);
        mx = mx > e0 ? mx : e0;
        mn = mn > e1 ? mn : e1;
    }
    #pragma unroll
    for (int o = 16; o; o >>= 1) {
        unsigned a = __shfl_xor_sync(0xffffffffu, mx, o);
        unsigned b = __shfl_xor_sync(0xffffffffu, mn, o);
        mx = mx > a ? mx : a;
        mn = mn > b ? mn : b;
    }
    if ((threadIdx.x & 31) == 0) {
        atomicMax(&g_mm[0], mx);
        atomicMax(&g_mm[1], mn);
    }
}

// quantize to s8, layout [r][seg][m][16]
__global__ void k_quant(const float* __restrict__ w) {
    int idx = blockIdx.x * blockDim.x + threadIdx.x;
    if (idx >= COUT * DTOT) return;
    float mx = decf(g_mm[0]);
    float mn = -decf(g_mm[1]);
    float scale = 15.0f / (mx - mn + 1e-9f);
    int m = idx / DTOT;
    int d = idx - m * DTOT;
    float q = fminf(fmaxf(rintf(w[idx] * scale), -7.0f), 7.0f);
    int r = d >> 6, kk = d & 63;
    g_wq[((r * 4 + (kk >> 4)) << 12) + m * 16 + (kk & 15)] = (signed char)(int)q;
}

// zero-padded input copy (float4 stores) + offset table + ticket reset
__global__ void k_pad(const float* __restrict__ inp) {
    int idx = blockIdx.x * blockDim.x + threadIdx.x;
    if (idx == 0) g_tick = (unsigned)(NCTA * 8);   // 2368 statically assigned
    if (idx < DTOT) {
        int c = idx / 9, e = idx - 9 * c;
        int dy = e / 3, dx = e - 3 * dy;
        g_ctab[idx] = c * PADIMG + dy * PADROW + dx;
    }
    const int N4 = 16 * 128 * (PADIMG / 4);
    if (idx >= N4) return;
    int bc  = idx / (PADIMG / 4);
    int rem = idx - bc * (PADIMG / 4);
    int yy  = rem / (PADROW / 4);
    int c4  = rem - yy * (PADROW / 4);
    const float* src = inp + bc * 1024 + (yy - 1) * 32;
    float4 v;
    #pragma unroll
    for (int j = 0; j < 4; j++) {
        int x = c4 * 4 + j;
        float f = 0.0f;
        if ((unsigned)(yy - 1) < 32u && (unsigned)(x - 1) < 32u)
            f = src[x - 1];
        ((float*)&v)[j] = f;
    }
    *(float4*)&g_xpad[(size_t)bc * PADIMG + yy * PADROW + c4 * 4] = v;
}

// im2col + exact 3-plane fixed-point split (scale 2^19)  [R12 version]
__global__ __launch_bounds__(256)
void k_im2col() {
    __shared__ int s_ct[64];
    const int bid = blockIdx.x;                 // 0..1151
    const int r   = bid >> 6;
    const int pix = ((bid & 63) << 8) + threadIdx.x;
    const int b   = pix >> 10;
    const int p10 = pix & 1023;
    const int py  = p10 >> 5;
    const int px  = p10 & 31;
    const float* __restrict__ xb =
        g_xpad + (size_t)b * (128 * PADIMG) + py * PADROW + px;

    if (threadIdx.x < 64) s_ct[threadIdx.x] = g_ctab[r * 64 + threadIdx.x];
    __syncthreads();

    #pragma unroll
    for (int seg = 0; seg < 4; seg++) {
        unsigned lo4[4], md4[4], hi4[4];
        #pragma unroll
        for (int w = 0; w < 4; w++) {
            int vi[4];
            #pragma unroll
            for (int e = 0; e < 4; e++) {
                float v = xb[s_ct[seg * 16 + w * 4 + e]];
                vi[e] = __float2int_rn(v * 524288.0f);
            }
            int t0 = (vi[0] + 128) >> 8, t1 = (vi[1] + 128) >> 8;
            int t2 = (vi[2] + 128) >> 8, t3 = (vi[3] + 128) >> 8;
            int u0 = (t0 + 128) >> 8, u1 = (t1 + 128) >> 8;
            int u2 = (t2 + 128) >> 8, u3 = (t3 + 128) >> 8;
            lo4[w] = pack_b0(vi[0], vi[1], vi[2], vi[3]);
            md4[w] = pack_b0(t0, t1, t2, t3);
            hi4[w] = pack_b0(u0, u1, u2, u3);
        }
        size_t base = ((((size_t)r * 3 + 0) * 4 + seg) * 16384 + pix) * 16;
        *(uint4*)&g_xq[base] = make_uint4(hi4[0], hi4[1], hi4[2], hi4[3]);
        base = ((((size_t)r * 3 + 1) * 4 + seg) * 16384 + pix) * 16;
        *(uint4*)&g_xq[base] = make_uint4(md4[0], md4[1], md4[2], md4[3]);
        base = ((((size_t)r * 3 + 2) * 4 + seg) * 16384 + pix) * 16;
        *(uint4*)&g_xq[base] = make_uint4(lo4[0], lo4[1], lo4[2], lo4[3]);
    }
}

// ---------------- main kernel: 16x64 tiles + global work stealing ----------------
__global__ __launch_bounds__(256, 2)
void k_onn_main(float* __restrict__ out) {
    const int tid  = threadIdx.x;
    const int lane = tid & 31;
    const int wid  = tid >> 5;
    const int bid  = blockIdx.x;

    const signed char* __restrict__ xq = g_xq;
    const signed char* __restrict__ wq = g_wq;

    const unsigned laneq = (unsigned)(lane >> 2);
    const unsigned lane4 = (unsigned)(lane & 3) * 4u;

    int tile = bid * 8 + wid;           // static first tile (all 2368 warps)
    while (tile < NTILES) {
        const int gp0 = (tile >> 2) * 16;
        const int ch0 = (tile & 3) * 64;

        unsigned pixoff[2];
        #pragma unroll
        for (int qh = 0; qh < 2; qh++)
            pixoff[qh] = (unsigned)(gp0 + (int)laneq + qh * 8) * 16u + lane4;

        unsigned cnt[8];
        #pragma unroll
        for (int i = 0; i < 8; i++) cnt[i] = 0u;

        #pragma unroll 1
        for (int r = 0; r < RCH; r++) {
            // ---- A fragments (mt = 0 only): 16 LDG ----
            unsigned af[2][2][4];      // [pl][ks][q]
            #pragma unroll
            for (int pl = 0; pl < 2; pl++) {
                const unsigned pbase = (unsigned)(r * 3 + pl) << 20;
                #pragma unroll
                for (int ks = 0; ks < 2; ks++)
                    #pragma unroll
                    for (int q = 0; q < 4; q++) {
                        const unsigned seg = (unsigned)(ks * 2 + (q >> 1));
                        af[pl][ks][q] = *(const unsigned*)
                            (xq + pbase + (seg << 18) + pixoff[q & 1]);
                    }
            }
            // ---- B fragments: 32 LDG ----
            unsigned bfa[4][2][2][2];  // [ng][ntl][ks][q]
            #pragma unroll
            for (int ng = 0; ng < 4; ng++)
                #pragma unroll
                for (int ntl = 0; ntl < 2; ntl++) {
                    const unsigned n = (unsigned)(ch0 + ng * 16 + ntl * 8
                                                  + (int)laneq);
                    #pragma unroll
                    for (int ks = 0; ks < 2; ks++)
                        #pragma unroll
                        for (int q = 0; q < 2; q++)
                            bfa[ng][ntl][ks][q] = *(const unsigned*)
                                (wq + ((unsigned)(r * 4 + ks * 2 + q) << 12)
                                    + n * 16u + lane4);
                }

            // ---- compute ----
            #pragma unroll
            for (int ng = 0; ng < 4; ng++) {
                int acc[2][4];         // [ntl][q]
                #pragma unroll
                for (int t = 0; t < 2; t++)
                    #pragma unroll
                    for (int q = 0; q < 4; q++) acc[t][q] = 0;

                #pragma unroll
                for (int pl = 0; pl < 2; pl++) {
                    if (pl) {
                        #pragma unroll
                        for (int t = 0; t < 2; t++)
                            #pragma unroll
                            for (int q = 0; q < 4; q++) acc[t][q] <<= 8;
                    }
                    #pragma unroll
                    for (int ntl = 0; ntl < 2; ntl++) {
                        imma(acc[ntl], af[pl][0], bfa[ng][ntl][0]);
                        imma(acc[ntl], af[pl][1], bfa[ng][ntl][1]);
                    }
                }

                unsigned cm = 0u;
                #pragma unroll
                for (int t = 0; t < 2; t++) {
                    unsigned inc = 0;
                    #pragma unroll
                    for (int q = 0; q < 4; q++) {
                        int v = acc[t][q];
                        inc |= ((unsigned)(~v) >> 31) << (8 * q);
                        if ((unsigned)(v + 224) <= 448u) cm |= 1u << (t * 4 + q);
                    }
                    cnt[ng * 2 + t] += inc;
                }

                // exact lo-plane fixup (rare), from L2
                while (cm) {
                    const int i = __ffs(cm) - 1;
                    cm &= cm - 1;
                    const int t = i >> 2, q = i & 3;
                    const int row = gp0 + (int)laneq + ((q & 2) ? 8 : 0);
                    const int col = ch0 + ng * 16 + t * 8 + 2 * (lane & 3)
                                  + (q & 1);
                    int slo = 0;
                    #pragma unroll
                    for (int kk = 0; kk < 16; kk++) {
                        const int xl = *(const int*)
                            (xq + ((unsigned)(r * 3 + 2) << 20)
                                + ((unsigned)(kk >> 2) << 18)
                                + (unsigned)row * 16u + (unsigned)(kk & 3) * 4u);
                        const int wc = *(const int*)
                            (wq + ((unsigned)(r * 4 + (kk >> 2)) << 12)
                                + (unsigned)col * 16u + (unsigned)(kk & 3) * 4u);
                        slo = __dp4a(xl, wc, slo);
                    }
                    const int S = (acc[t][q] << 8) + slo;
                    const unsigned ob = (unsigned)(~acc[t][q]) >> 31;
                    const unsigned nb = (unsigned)(~S) >> 31;
                    cnt[ng * 2 + t] += (nb - ob) << (8 * q);
                }
            }
        }

        // ---- store: direct STG (32B-sector segments) ----
        const int b   = gp0 >> 10;
        const int p10 = gp0 & 1023;
        float* __restrict__ ob = out + (size_t)b * (COUT * 1024) + p10;
        #pragma unroll
        for (int g = 0; g < 8; g++) {
            const int chb = ch0 + (g >> 1) * 16 + (g & 1) * 8 + 2 * (lane & 3);
            #pragma unroll
            for (int q = 0; q < 4; q++) {
                const int cc = chb + (q & 1);
                const int pp = (int)laneq + ((q & 2) ? 8 : 0);
                ob[(size_t)cc * 1024 + pp] =
                    (float)((cnt[g] >> (8 * q)) & 255u);
            }
        }

        // ---- steal next tile (global ticket) ----
        if (lane == 0) tile = (int)atomicAdd(&g_tick, 1u);
        tile = __shfl_sync(0xffffffffu, tile, 0);
    }
}

// ---------------- launcher ----------------
extern "C" void kernel_launch(void* const* d_in, const int* in_sizes, int n_in,
                              void* d_out, int out_size) {
    const float* inp    = (const float*)d_in[0];  // [16,128,32,32]
    const float* weight = (const float*)d_in[1];  // [256,128,3,3]
    float* out          = (float*)d_out;          // [16,256,32,32]

    const int nw = COUT * DTOT;
    const int n4 = 16 * 128 * (PADIMG / 4);

    k_minmax<<<256, 256>>>(weight, nw);
    k_quant<<<(nw + 255) / 256, 256>>>(weight);
    k_pad<<<(n4 + 255) / 256, 256>>>(inp);
    k_im2col<<<RCH * 64, 256>>>();
    k_onn_main<<<NCTA, 256>>>(out);
}

// round 15
// speedup vs baseline: 1.8127x; 1.1179x over previous
#include <cuda_runtime.h>
#include <cstdint>

// ---------------- problem constants ----------------
#define CIN   128
#define COUT  256
#define DTOT  1152
#define RCH   18
#define NCTA  296
#define NTILES 4096          // 1024 pixel groups x 4 channel groups (16x64 tiles)
#define NT_T  2176           // tensor-first pool
#define NT_D  (NTILES - NT_T)

#define PADROW 36
#define PADIMG (34 * PADROW)

// ---------------- device scratch ----------------
__device__ unsigned g_mm[2] = {0u, 0u};
__device__ unsigned g_tkT, g_tkD;
__device__ __align__(16) signed char g_wq[RCH * 4 * 256 * 16];   // [r][seg][m][16]
__device__ __align__(16) signed char g_xq[(size_t)RCH * 3 * 4 * 16384 * 16]; // [r][pl][seg][pix][16]
__device__ __align__(16) float g_xpad[16 * 128 * PADIMG];
__device__ int   g_ctab[DTOT];

// ---------------- helpers ----------------
__device__ __forceinline__ unsigned encf(float f) {
    int b = __float_as_int(f);
    return (b < 0) ? ~(unsigned)b : ((unsigned)b | 0x80000000u);
}
__device__ __forceinline__ float decf(unsigned u) {
    int b = (u & 0x80000000u) ? (int)(u & 0x7fffffffu) : ~(int)u;
    return __int_as_float(b);
}
__device__ __forceinline__ void imma(int* d, const unsigned* a, const unsigned* b) {
    asm volatile(
        "mma.sync.aligned.m16n8k32.row.col.s32.s8.s8.s32 "
        "{%0,%1,%2,%3}, {%4,%5,%6,%7}, {%8,%9}, {%0,%1,%2,%3};"
        : "+r"(d[0]), "+r"(d[1]), "+r"(d[2]), "+r"(d[3])
        : "r"(a[0]), "r"(a[1]), "r"(a[2]), "r"(a[3]),
          "r"(b[0]), "r"(b[1]));
}
__device__ __forceinline__ unsigned prmt(unsigned a, unsigned b, unsigned c) {
    unsigned r;
    asm("prmt.b32 %0, %1, %2, %3;" : "=r"(r) : "r"(a), "r"(b), "r"(c));
    return r;
}
__device__ __forceinline__ unsigned pack_b0(int v0, int v1, int v2, int v3) {
    return prmt(prmt((unsigned)v0, (unsigned)v1, 0x0040),
                prmt((unsigned)v2, (unsigned)v3, 0x0040), 0x5410);
}
__device__ __forceinline__ int dp4x4(uint4 a, uint4 b, int acc) {
    acc = __dp4a((int)a.x, (int)b.x, acc);
    acc = __dp4a((int)a.y, (int)b.y, acc);
    acc = __dp4a((int)a.z, (int)b.z, acc);
    acc = __dp4a((int)a.w, (int)b.w, acc);
    return acc;
}

// ---------------- pre-kernels (R12/R14 proven) ----------------
__global__ void k_minmax(const float* __restrict__ w, int n) {
    unsigned mx = 0u, mn = 0u;
    for (int i = blockIdx.x * blockDim.x + threadIdx.x; i < n;
         i += gridDim.x * blockDim.x) {
        float f = w[i];
        unsigned e0 = encf(f), e1 = encf(-f);
        mx = mx > e0 ? mx : e0;
        mn = mn > e1 ? mn : e1;
    }
    #pragma unroll
    for (int o = 16; o; o >>= 1) {
        unsigned a = __shfl_xor_sync(0xffffffffu, mx, o);
        unsigned b = __shfl_xor_sync(0xffffffffu, mn, o);
        mx = mx > a ? mx : a;
        mn = mn > b ? mn : b;
    }
    if ((threadIdx.x & 31) == 0) {
        atomicMax(&g_mm[0], mx);
        atomicMax(&g_mm[1], mn);
    }
}

__global__ void k_quant(const float* __restrict__ w) {
    int idx = blockIdx.x * blockDim.x + threadIdx.x;
    if (idx >= COUT * DTOT) return;
    float mx = decf(g_mm[0]);
    float mn = -decf(g_mm[1]);
    float scale = 15.0f / (mx - mn + 1e-9f);
    int m = idx / DTOT;
    int d = idx - m * DTOT;
    float q = fminf(fmaxf(rintf(w[idx] * scale), -7.0f), 7.0f);
    int r = d >> 6, kk = d & 63;
    g_wq[((r * 4 + (kk >> 4)) << 12) + m * 16 + (kk & 15)] = (signed char)(int)q;
}

__global__ void k_pad(const float* __restrict__ inp) {
    int idx = blockIdx.x * blockDim.x + threadIdx.x;
    if (idx == 0) { g_tkT = 0u; g_tkD = 0u; }
    if (idx < DTOT) {
        int c = idx / 9, e = idx - 9 * c;
        int dy = e / 3, dx = e - 3 * dy;
        g_ctab[idx] = c * PADIMG + dy * PADROW + dx;
    }
    const int N4 = 16 * 128 * (PADIMG / 4);
    if (idx >= N4) return;
    int bc  = idx / (PADIMG / 4);
    int rem = idx - bc * (PADIMG / 4);
    int yy  = rem / (PADROW / 4);
    int c4  = rem - yy * (PADROW / 4);
    const float* src = inp + bc * 1024 + (yy - 1) * 32;
    float4 v;
    #pragma unroll
    for (int j = 0; j < 4; j++) {
        int x = c4 * 4 + j;
        float f = 0.0f;
        if ((unsigned)(yy - 1) < 32u && (unsigned)(x - 1) < 32u)
            f = src[x - 1];
        ((float*)&v)[j] = f;
    }
    *(float4*)&g_xpad[(size_t)bc * PADIMG + yy * PADROW + c4 * 4] = v;
}

__global__ __launch_bounds__(256)
void k_im2col() {
    __shared__ int s_ct[64];
    const int bid = blockIdx.x;
    const int r   = bid >> 6;
    const int pix = ((bid & 63) << 8) + threadIdx.x;
    const int b   = pix >> 10;
    const int p10 = pix & 1023;
    const int py  = p10 >> 5;
    const int px  = p10 & 31;
    const float* __restrict__ xb =
        g_xpad + (size_t)b * (128 * PADIMG) + py * PADROW + px;

    if (threadIdx.x < 64) s_ct[threadIdx.x] = g_ctab[r * 64 + threadIdx.x];
    __syncthreads();

    #pragma unroll
    for (int seg = 0; seg < 4; seg++) {
        unsigned lo4[4], md4[4], hi4[4];
        #pragma unroll
        for (int w = 0; w < 4; w++) {
            int vi[4];
            #pragma unroll
            for (int e = 0; e < 4; e++) {
                float v = xb[s_ct[seg * 16 + w * 4 + e]];
                vi[e] = __float2int_rn(v * 524288.0f);
            }
            int t0 = (vi[0] + 128) >> 8, t1 = (vi[1] + 128) >> 8;
            int t2 = (vi[2] + 128) >> 8, t3 = (vi[3] + 128) >> 8;
            int u0 = (t0 + 128) >> 8, u1 = (t1 + 128) >> 8;
            int u2 = (t2 + 128) >> 8, u3 = (t3 + 128) >> 8;
            lo4[w] = pack_b0(vi[0], vi[1], vi[2], vi[3]);
            md4[w] = pack_b0(t0, t1, t2, t3);
            hi4[w] = pack_b0(u0, u1, u2, u3);
        }
        size_t base = ((((size_t)r * 3 + 0) * 4 + seg) * 16384 + pix) * 16;
        *(uint4*)&g_xq[base] = make_uint4(hi4[0], hi4[1], hi4[2], hi4[3]);
        base = ((((size_t)r * 3 + 1) * 4 + seg) * 16384 + pix) * 16;
        *(uint4*)&g_xq[base] = make_uint4(md4[0], md4[1], md4[2], md4[3]);
        base = ((((size_t)r * 3 + 2) * 4 + seg) * 16384 + pix) * 16;
        *(uint4*)&g_xq[base] = make_uint4(lo4[0], lo4[1], lo4[2], lo4[3]);
    }
}

// ---------------- tensor-path tile (R14) ----------------
__device__ __noinline__ void tensor_tile(int tile, int lane,
                                         float* __restrict__ out) {
    const signed char* __restrict__ xq = g_xq;
    const signed char* __restrict__ wq = g_wq;
    const unsigned laneq = (unsigned)(lane >> 2);
    const unsigned lane4 = (unsigned)(lane & 3) * 4u;

    const int gp0 = (tile >> 2) * 16;
    const int ch0 = (tile & 3) * 64;

    unsigned pixoff[2];
    #pragma unroll
    for (int qh = 0; qh < 2; qh++)
        pixoff[qh] = (unsigned)(gp0 + (int)laneq + qh * 8) * 16u + lane4;

    unsigned cnt[8];
    #pragma unroll
    for (int i = 0; i < 8; i++) cnt[i] = 0u;

    #pragma unroll 1
    for (int r = 0; r < RCH; r++) {
        unsigned af[2][2][4];
        #pragma unroll
        for (int pl = 0; pl < 2; pl++) {
            const unsigned pbase = (unsigned)(r * 3 + pl) << 20;
            #pragma unroll
            for (int ks = 0; ks < 2; ks++)
                #pragma unroll
                for (int q = 0; q < 4; q++) {
                    const unsigned seg = (unsigned)(ks * 2 + (q >> 1));
                    af[pl][ks][q] = *(const unsigned*)
                        (xq + pbase + (seg << 18) + pixoff[q & 1]);
                }
        }
        unsigned bfa[4][2][2][2];
        #pragma unroll
        for (int ng = 0; ng < 4; ng++)
            #pragma unroll
            for (int ntl = 0; ntl < 2; ntl++) {
                const unsigned n = (unsigned)(ch0 + ng * 16 + ntl * 8 + (int)laneq);
                #pragma unroll
                for (int ks = 0; ks < 2; ks++)
                    #pragma unroll
                    for (int q = 0; q < 2; q++)
                        bfa[ng][ntl][ks][q] = *(const unsigned*)
                            (wq + ((unsigned)(r * 4 + ks * 2 + q) << 12)
                                + n * 16u + lane4);
            }

        #pragma unroll
        for (int ng = 0; ng < 4; ng++) {
            int acc[2][4];
            #pragma unroll
            for (int t = 0; t < 2; t++)
                #pragma unroll
                for (int q = 0; q < 4; q++) acc[t][q] = 0;

            #pragma unroll
            for (int pl = 0; pl < 2; pl++) {
                if (pl) {
                    #pragma unroll
                    for (int t = 0; t < 2; t++)
                        #pragma unroll
                        for (int q = 0; q < 4; q++) acc[t][q] <<= 8;
                }
                #pragma unroll
                for (int ntl = 0; ntl < 2; ntl++) {
                    imma(acc[ntl], af[pl][0], bfa[ng][ntl][0]);
                    imma(acc[ntl], af[pl][1], bfa[ng][ntl][1]);
                }
            }

            unsigned cm = 0u;
            #pragma unroll
            for (int t = 0; t < 2; t++) {
                unsigned inc = 0;
                #pragma unroll
                for (int q = 0; q < 4; q++) {
                    int v = acc[t][q];
                    inc |= ((unsigned)(~v) >> 31) << (8 * q);
                    if ((unsigned)(v + 224) <= 448u) cm |= 1u << (t * 4 + q);
                }
                cnt[ng * 2 + t] += inc;
            }

            while (cm) {
                const int i = __ffs(cm) - 1;
                cm &= cm - 1;
                const int t = i >> 2, q = i & 3;
                const int row = gp0 + (int)laneq + ((q & 2) ? 8 : 0);
                const int col = ch0 + ng * 16 + t * 8 + 2 * (lane & 3) + (q & 1);
                int slo = 0;
                #pragma unroll
                for (int kk = 0; kk < 4; kk++) {
                    uint4 xl = *(const uint4*)
                        (xq + ((unsigned)(r * 3 + 2) << 20)
                            + ((unsigned)kk << 18) + (unsigned)row * 16u);
                    uint4 wc = *(const uint4*)
                        (wq + ((unsigned)(r * 4 + kk) << 12)
                            + (unsigned)col * 16u);
                    slo = dp4x4(xl, wc, slo);
                }
                const int S = (acc[t][q] << 8) + slo;
                const unsigned ob = (unsigned)(~acc[t][q]) >> 31;
                const unsigned nb = (unsigned)(~S) >> 31;
                cnt[ng * 2 + t] += (nb - ob) << (8 * q);
            }
        }
    }

    const int b   = gp0 >> 10;
    const int p10 = gp0 & 1023;
    float* __restrict__ ob = out + (size_t)b * (COUT * 1024) + p10;
    #pragma unroll
    for (int g = 0; g < 8; g++) {
        const int chb = ch0 + (g >> 1) * 16 + (g & 1) * 8 + 2 * (lane & 3);
        #pragma unroll
        for (int q = 0; q < 4; q++) {
            const int cc = chb + (q & 1);
            const int pp = (lane >> 2) + ((q & 2) ? 8 : 0);
            ob[(size_t)cc * 1024 + pp] = (float)((cnt[g] >> (8 * q)) & 255u);
        }
    }
}

// ---------------- dp4a-path tile ----------------
__device__ __noinline__ void dp4a_tile(int tile, int lane, uint4* As,
                                       float* __restrict__ out) {
    const signed char* __restrict__ xq = g_xq;
    const signed char* __restrict__ wq = g_wq;

    const int gp0 = (tile >> 2) * 16;
    const int ch0 = (tile & 3) * 64;
    const int c0  = ch0 + lane * 2;       // this lane's channel pair

    unsigned cnt[8];
    #pragma unroll
    for (int i = 0; i < 8; i++) cnt[i] = 0u;

    #pragma unroll 1
    for (int r = 0; r < RCH; r++) {
        __syncwarp();                     // prior chunk's reads done
        // stage A slab (3 planes x 16 pix x 64B = 192 uint4) into SMEM
        #pragma unroll
        for (int i = 0; i < 6; i++) {
            const int u   = lane + 32 * i;
            const int pl  = u >> 6;
            const int rem = u & 63;
            const int seg = rem >> 4;
            const int p   = rem & 15;
            uint4 v = *(const uint4*)
                (xq + ((unsigned)(r * 3 + pl) << 20) + ((unsigned)seg << 18)
                    + (unsigned)(gp0 + p) * 16u);
            As[(pl * 16 + p) * 4 + seg] = v;
        }
        // W for 2 channels
        uint4 w0[4], w1[4];
        #pragma unroll
        for (int seg = 0; seg < 4; seg++) {
            w0[seg] = *(const uint4*)
                (wq + ((unsigned)(r * 4 + seg) << 12) + (unsigned)c0 * 16u);
            w1[seg] = *(const uint4*)
                (wq + ((unsigned)(r * 4 + seg) << 12) + (unsigned)(c0 + 1) * 16u);
        }
        __syncwarp();                     // staging visible

        #pragma unroll
        for (int p = 0; p < 16; p++) {
            const uint4* ah = &As[(0 * 16 + p) * 4];
            const uint4* am = &As[(1 * 16 + p) * 4];
            int sh0 = 0, sh1 = 0, sm0 = 0, sm1 = 0;
            #pragma unroll
            for (int seg = 0; seg < 4; seg++) {
                uint4 a = ah[seg];
                sh0 = dp4x4(a, w0[seg], sh0);
                sh1 = dp4x4(a, w1[seg], sh1);
                uint4 m = am[seg];
                sm0 = dp4x4(m, w0[seg], sm0);
                sm1 = dp4x4(m, w1[seg], sm1);
            }
            int s0 = (sh0 << 8) + sm0;
            int s1 = (sh1 << 8) + sm1;
            if ((unsigned)(s0 + 224) <= 448u) {
                const uint4* al = &As[(2 * 16 + p) * 4];
                int slo = 0;
                #pragma unroll
                for (int seg = 0; seg < 4; seg++)
                    slo = dp4x4(al[seg], w0[seg], slo);
                s0 = (s0 << 8) + slo;
            }
            if ((unsigned)(s1 + 224) <= 448u) {
                const uint4* al = &As[(2 * 16 + p) * 4];
                int slo = 0;
                #pragma unroll
                for (int seg = 0; seg < 4; seg++)
                    slo = dp4x4(al[seg], w1[seg], slo);
                s1 = (s1 << 8) + slo;
            }
            const int sh8 = 8 * (p & 3);
            cnt[p >> 2]       += (((unsigned)(~s0)) >> 31) << sh8;
            cnt[4 + (p >> 2)] += (((unsigned)(~s1)) >> 31) << sh8;
        }
    }

    // store: 2 channels x 16 contiguous pixels (4 x STG.128 each)
    const int b   = gp0 >> 10;
    const int p10 = gp0 & 1023;
    #pragma unroll
    for (int c = 0; c < 2; c++) {
        float* __restrict__ o = out + (size_t)b * (COUT * 1024)
                              + (size_t)(c0 + c) * 1024 + p10;
        #pragma unroll
        for (int g = 0; g < 4; g++) {
            unsigned v = cnt[c * 4 + g];
            float4 f;
            f.x = (float)( v        & 255u);
            f.y = (float)((v >>  8) & 255u);
            f.z = (float)((v >> 16) & 255u);
            f.w = (float)((v >> 24) & 255u);
            *(float4*)&o[g * 4] = f;
        }
    }
}

// ---------------- main kernel: dual-pipe (IMMA + dp4a) ----------------
__global__ __launch_bounds__(256, 2)
void k_onn_main(float* __restrict__ out) {
    __shared__ __align__(16) uint4 s_a[4][192];   // 3KB per dp4a warp

    const int tid  = threadIdx.x;
    const int lane = tid & 31;
    const int wid  = tid >> 5;

    if (wid < 4) {
        // tensor warps: drain pool T, then help with pool D
        for (;;) {
            int t;
            if (lane == 0) t = (int)atomicAdd(&g_tkT, 1u);
            t = __shfl_sync(0xffffffffu, t, 0);
            if (t >= NT_T) break;
            tensor_tile(t, lane, out);
        }
        for (;;) {
            int t;
            if (lane == 0) t = (int)atomicAdd(&g_tkD, 1u);
            t = __shfl_sync(0xffffffffu, t, 0);
            if (t >= NT_D) break;
            tensor_tile(NT_T + t, lane, out);
        }
    } else {
        uint4* As = s_a[wid - 4];
        // dp4a warps: drain pool D, then help with pool T
        for (;;) {
            int t;
            if (lane == 0) t = (int)atomicAdd(&g_tkD, 1u);
            t = __shfl_sync(0xffffffffu, t, 0);
            if (t >= NT_D) break;
            dp4a_tile(NT_T + t, lane, As, out);
        }
        for (;;) {
            int t;
            if (lane == 0) t = (int)atomicAdd(&g_tkT, 1u);
            t = __shfl_sync(0xffffffffu, t, 0);
            if (t >= NT_T) break;
            dp4a_tile(t, lane, As, out);
        }
    }
}

// ---------------- launcher ----------------
extern "C" void kernel_launch(void* const* d_in, const int* in_sizes, int n_in,
                              void* d_out, int out_size) {
    const float* inp    = (const float*)d_in[0];  // [16,128,32,32]
    const float* weight = (const float*)d_in[1];  // [256,128,3,3]
    float* out          = (float*)d_out;          // [16,256,32,32]

    const int nw = COUT * DTOT;
    const int n4 = 16 * 128 * (PADIMG / 4);

    k_minmax<<<256, 256>>>(weight, nw);
    k_quant<<<(nw + 255) / 256, 256>>>(weight);
    k_pad<<<(n4 + 255) / 256, 256>>>(inp);
    k_im2col<<<RCH * 64, 256>>>();
    k_onn_main<<<NCTA, 256>>>(out);
}